// round 12
// baseline (speedup 1.0000x reference)
#include <cuda_runtime.h>
#include <cuda_bf16.h>
#include <cstdint>

#define NN   128
#define DD   128
#define EE   128
#define NG   8
#define VDIM 300

// ---------------- device scratch (allocation-free) ----------------
__device__ float g_base[NN * DD];
__device__ float g_vacc[NG][NN * DD];      // child-transform sums; zeroed by k_reset
__device__ float g_u[NG][NN][DD];          // path vectors, idx 0..plen-1
__device__ float g_w2[NG][DD];
__device__ float g_cconst[NG];
__device__ float g_dscore;
__device__ int   g_cnt[NG][NN];            // child-completion counters
__device__ int   g_par[NG][NN];
__device__ int   g_cc[NG][NN];
__device__ unsigned char g_inpath[NG][NN];
__device__ int   g_plen[NG];
__device__ int   g_plist[NG][NN];
__device__ int   g_pedge[NG][NN];
// flags (zeroed by k_reset every launch)
__device__ int   c_parse[NG];
__device__ int   c_fold[NG];
__device__ int   c_u[NG][NN];              // per-path-index availability
__device__ int   c_base[NN];
__device__ int   c_dscore;

// =============== reset: runs first every launch; immune to dirty state ===============
__global__ void k_reset() {
    int i = blockIdx.x * blockDim.x + threadIdx.x;   // 0..32767
    ((float4*)g_vacc)[i] = make_float4(0.f, 0.f, 0.f, 0.f);
    if (i < NG) { c_parse[i] = 0; c_fold[i] = 0; }
    if (i < NN) c_base[i] = 0;
    if (i < NG * NN) { ((int*)g_cnt)[i] = 0; ((int*)c_u)[i] = 0; }
    if (i == 0) c_dscore = 0;
}

// ---------------- helpers ----------------
__device__ __forceinline__ void warp_spin_ge(int* p, int tgt) {
    if ((threadIdx.x & 31) == 0) {
        volatile int* vp = (volatile int*)p;
        while (*vp < tgt) { }
    }
    __syncwarp();
    __threadfence();
}

// y[k] = sum_d v[d] * W[d*DD + k] ; v lane-distributed float4 (lane q owns d=4q..4q+3)
// FULLY unrolled: 128 independent LDG.128 in straight-line code -> deep MLP.
__device__ __forceinline__ float4 matvec_u(const float* __restrict__ W, float4 v, int k0) {
    float y0 = 0.f, y1 = 0.f, y2 = 0.f, y3 = 0.f;
    const float* Wl = W + k0;
#pragma unroll
    for (int q = 0; q < 32; q++) {
        float a0 = __shfl_sync(0xffffffffu, v.x, q);
        float a1 = __shfl_sync(0xffffffffu, v.y, q);
        float a2 = __shfl_sync(0xffffffffu, v.z, q);
        float a3 = __shfl_sync(0xffffffffu, v.w, q);
        float4 w0 = __ldg((const float4*)(Wl + (4 * q + 0) * DD));
        float4 w1 = __ldg((const float4*)(Wl + (4 * q + 1) * DD));
        float4 w2 = __ldg((const float4*)(Wl + (4 * q + 2) * DD));
        float4 w3 = __ldg((const float4*)(Wl + (4 * q + 3) * DD));
        y0 += a0 * w0.x + a1 * w1.x + a2 * w2.x + a3 * w3.x;
        y1 += a0 * w0.y + a1 * w1.y + a2 * w2.y + a3 * w3.y;
        y2 += a0 * w0.z + a1 * w1.z + a2 * w2.z + a3 * w3.z;
        y3 += a0 * w0.w + a1 * w1.w + a2 * w2.w + a3 * w3.w;
    }
    return make_float4(y0, y1, y2, y3);
}

__device__ __forceinline__ float warp_red(float v) {
    for (int o = 16; o; o >>= 1) v += __shfl_xor_sync(0xffffffffu, v, o);
    return v;
}

// ---------------- the fused kernel ----------------
__global__ void __launch_bounds__(256, 1)
k_fused(const int* __restrict__ data, const int* __restrict__ graphs,
        const int* __restrict__ edges, const int* __restrict__ posp,
        const float* __restrict__ dv, const float* __restrict__ dw,
        const float* __restrict__ db, const float* __restrict__ ew,
        const float* __restrict__ ebias, const float* __restrict__ sew,
        const float* __restrict__ sdw, const float* __restrict__ sb,
        float* __restrict__ out) {
    __shared__ float s_dv[VDIM];
    __shared__ float s_half[2][DD];
    __shared__ int s_par[NN], s_cc[NN];
    __shared__ unsigned s_rm[4];

    int b = blockIdx.x, t = threadIdx.x;
    int wid = t >> 5, lane = t & 31;
    int k0 = lane * 4;

    // ===== phase 1: base embedding for node b =====
    {
        const float* vr = dv + (size_t)data[b] * VDIM;
        for (int i = t; i < VDIM; i += 256) s_dv[i] = vr[i];
        __syncthreads();
        int k = t & 127, half = t >> 7;
        float acc = 0.f;
        int vs = half * 150, ve = vs + 150;
#pragma unroll 10
        for (int v = vs; v < ve; v++) acc += s_dv[v] * __ldg(dw + v * DD + k);
        s_half[half][k] = acc;
        __syncthreads();
        if (t < DD) g_base[b * DD + t] = s_half[0][t] + s_half[1][t] + db[t];
        __syncthreads();
        if (t == 0) { __threadfence(); atomicAdd(&c_base[b], 1); }
    }

    // ===== phase 2: tree parse (CTAs 0..7) =====
    if (b < NG) {
        int g = b;
        if (t < NN) {
            int off = graphs[g * NN + t];
            bool isroot = (off == 0);
            int par = isroot ? -1 : ((t + off < NN) ? t + off : -1);
            unsigned bm = __ballot_sync(0xffffffffu, isroot);
            if (lane == 0) s_rm[wid] = bm;
            s_par[t] = par; s_cc[t] = 0;
        }
        __syncthreads();
        if (t == 0) {
            int prev = -1;
            for (int q = 0; q < 4; q++) {
                unsigned mm = s_rm[q];
                while (mm) {
                    int bb = __ffs(mm) - 1; mm &= mm - 1;
                    int r = q * 32 + bb;
                    if (prev >= 0) { int p = prev + r; s_par[prev] = (p < NN) ? p : -1; }
                    prev = r;
                }
            }
            s_par[prev] = -1;   // final root
        }
        __syncthreads();
        if (t < NN) { int p = s_par[t]; if (p >= 0) atomicAdd(&s_cc[p], 1); }
        __syncthreads();
        if (t == 0) {
            int plen = 0, p = *posp;
            while (p >= 0) {
                g_plist[g][plen] = p;
                g_pedge[g][plen] = edges[p];
                plen++;
                p = s_par[p];
            }
            g_plen[g] = plen;
        }
        __syncthreads();
        if (t < NN) {
            g_par[g][t] = s_par[t];
            g_cc[g][t] = s_cc[t];
            g_inpath[g][t] = 0;
        }
        __syncthreads();
        if (t == 0) {
            int plen = g_plen[g];
            for (int i = 0; i < plen; i++) g_inpath[g][g_plist[g][i]] = 1;
            __threadfence();
            atomicAdd(&c_parse[g], 1);
        }
    }

    // ===== phase 3: dataflow vector pass, warp = (g, n) =====
    {
        int Wd = b * 8 + wid, g = Wd >> 7, n = Wd & 127;
        warp_spin_ge(&c_parse[g], 1);

        if (g_inpath[g][n]) {
            int plen = g_plen[g];
            int idx = 0;
            while (g_plist[g][idx] != n) idx++;
            if (idx == plen - 1) {                     // root: fold early
                if (plen > 1) {
                    int er = g_pedge[g][plen - 1];
                    float4 sv = *(const float4*)(sew + k0);
                    const float* Wb = ew + (size_t)er * (DD * DD);
                    float w20 = 0.f, w21 = 0.f, w22 = 0.f, w23 = 0.f;
#pragma unroll
                    for (int jq = 0; jq < 32; jq++) {
                        float s0 = __shfl_sync(0xffffffffu, sv.x, jq);
                        float s1 = __shfl_sync(0xffffffffu, sv.y, jq);
                        float s2 = __shfl_sync(0xffffffffu, sv.z, jq);
                        float s3 = __shfl_sync(0xffffffffu, sv.w, jq);
                        float4 r0 = __ldg((const float4*)(Wb + (k0 + 0) * DD + jq * 4));
                        float4 r1 = __ldg((const float4*)(Wb + (k0 + 1) * DD + jq * 4));
                        float4 r2 = __ldg((const float4*)(Wb + (k0 + 2) * DD + jq * 4));
                        float4 r3 = __ldg((const float4*)(Wb + (k0 + 3) * DD + jq * 4));
                        w20 += r0.x * s0 + r0.y * s1 + r0.z * s2 + r0.w * s3;
                        w21 += r1.x * s0 + r1.y * s1 + r1.z * s2 + r1.w * s3;
                        w22 += r2.x * s0 + r2.y * s1 + r2.z * s2 + r2.w * s3;
                        w23 += r3.x * s0 + r3.y * s1 + r3.z * s2 + r3.w * s3;
                    }
                    *(float4*)(&g_w2[g][0] + k0) = make_float4(w20, w21, w22, w23);
                    float4 sv2 = *(const float4*)(sew + k0);
                    float4 bb = *(const float4*)(ebias + er * DD + k0);
                    float cc = warp_red(bb.x * sv2.x + bb.y * sv2.y + bb.z * sv2.z + bb.w * sv2.w);
                    if (lane == 0) g_cconst[g] = cc;
                }
                __threadfence();
                if (lane == 0) atomicAdd(&c_fold[g], 1);
            }
            warp_spin_ge(&c_base[n], 1);
            float4 base4 = *(const float4*)(g_base + n * DD + k0);
            if (g == 0 && idx == 0) {                  // dscore (raw base[pos])
                float4 sd = *(const float4*)(sdw + k0);
                float p = warp_red(base4.x * sd.x + base4.y * sd.y + base4.z * sd.z + base4.w * sd.w);
                if (lane == 0) { g_dscore = p + sb[0]; __threadfence(); atomicAdd(&c_dscore, 1); }
            }
            int cc = g_cc[g][n];
            int tgt = cc - ((idx > 0) ? 1 : 0);        // path child does not signal
            float4 u = base4;
            if (tgt > 0) {
                warp_spin_ge(&g_cnt[g][n], tgt);
                float4 cs = __ldcg((const float4*)(&g_vacc[g][n * DD] + k0));
                u.x += cs.x; u.y += cs.y; u.z += cs.z; u.w += cs.w;
            }
            if (idx == 0 && cc > 0) {                  // v0 relu iff pos is internal
                u.x = fmaxf(u.x, 0.f); u.y = fmaxf(u.y, 0.f);
                u.z = fmaxf(u.z, 0.f); u.w = fmaxf(u.w, 0.f);
            }
            *(float4*)(&g_u[g][idx][0] + k0) = u;
            __threadfence(); __syncwarp();
            if (lane == 0) atomicAdd(&c_u[g][idx], 1);
        } else {
            int par = g_par[g][n];
            int cc = g_cc[g][n];
            warp_spin_ge(&c_base[n], 1);
            float4 v = *(const float4*)(g_base + n * DD + k0);
            if (cc > 0) {
                warp_spin_ge(&g_cnt[g][n], cc);
                float4 cs = __ldcg((const float4*)(&g_vacc[g][n * DD] + k0));
                v.x = fmaxf(v.x + cs.x, 0.f); v.y = fmaxf(v.y + cs.y, 0.f);
                v.z = fmaxf(v.z + cs.z, 0.f); v.w = fmaxf(v.w + cs.w, 0.f);
            }
            if (par >= 0) {
                int e = edges[n];
                float4 bb = *(const float4*)(ebias + e * DD + k0);
                float4 y = matvec_u(ew + (size_t)e * (DD * DD), v, k0);
                y.x += bb.x; y.y += bb.y; y.z += bb.z; y.w += bb.w;
                float* dst = &g_vacc[g][par * DD] + k0;
                atomicAdd(dst + 0, y.x); atomicAdd(dst + 1, y.y);
                atomicAdd(dst + 2, y.z); atomicAdd(dst + 3, y.w);
                __threadfence(); __syncwarp();
                if (lane == 0) atomicAdd(&g_cnt[g][par], 1);
            }
        }
    }

    // ===== phase 4: chains — 8 warps/CTA, 1 chain each, reg-resident state =====
    {
        int cg = b >> 4;
        int e = ((b & 15) << 3) + wid;

        warp_spin_ge(&c_parse[cg], 1);
        int plen = g_plen[cg];

        // step 0 (needs only v0)
        warp_spin_ge(&c_u[cg][0], 1);
        float4 v0 = *(const float4*)(&g_u[cg][0][0] + k0);
        float4 bb = *(const float4*)(ebias + e * DD + k0);
        float4 y = matvec_u(ew + (size_t)e * (DD * DD), v0, k0);
        y.x += bb.x; y.y += bb.y; y.z += bb.z; y.w += bb.w;

        if (plen == 1) {
            float4 sv = *(const float4*)(sew + k0);
            float p = warp_red(y.x * sv.x + y.y * sv.y + y.z * sv.z + y.w * sv.w);
            warp_spin_ge(&c_dscore, 1);
            if (lane == 0) out[cg * EE + e] = g_dscore + p;
        } else {
            warp_spin_ge(&c_u[cg][1], 1);
            float4 u1 = *(const float4*)(&g_u[cg][1][0] + k0);
            float4 m;
            m.x = fmaxf(y.x + u1.x, 0.f); m.y = fmaxf(y.y + u1.y, 0.f);
            m.z = fmaxf(y.z + u1.z, 0.f); m.w = fmaxf(y.w + u1.w, 0.f);
            for (int i = 2; i < plen; i++) {
                int eid = g_pedge[cg][i - 1];
                float4 bi = *(const float4*)(ebias + eid * DD + k0);
                float4 tt = matvec_u(ew + (size_t)eid * (DD * DD), m, k0);
                warp_spin_ge(&c_u[cg][i], 1);
                float4 u4 = *(const float4*)(&g_u[cg][i][0] + k0);
                m.x = fmaxf(tt.x + bi.x + u4.x, 0.f);
                m.y = fmaxf(tt.y + bi.y + u4.y, 0.f);
                m.z = fmaxf(tt.z + bi.z + u4.z, 0.f);
                m.w = fmaxf(tt.w + bi.w + u4.w, 0.f);
            }
            warp_spin_ge(&c_fold[cg], 1);
            float4 w2v = *(const float4*)(&g_w2[cg][0] + k0);
            float p = warp_red(m.x * w2v.x + m.y * w2v.y + m.z * w2v.z + m.w * w2v.w);
            warp_spin_ge(&c_dscore, 1);
            if (lane == 0) out[cg * EE + e] = g_dscore + g_cconst[cg] + p;
        }
    }
}

// =============== launcher ===============
extern "C" void kernel_launch(void* const* d_in, const int* in_sizes, int n_in,
                              void* d_out, int out_size) {
    const int*   data   = (const int*)d_in[0];
    const int*   graphs = (const int*)d_in[2];
    const int*   edges  = (const int*)d_in[3];
    const int*   pos    = (const int*)d_in[4];
    const float* dv     = (const float*)d_in[5];
    const float* dw     = (const float*)d_in[6];
    const float* db     = (const float*)d_in[7];
    const float* ew     = (const float*)d_in[8];
    const float* ebias  = (const float*)d_in[9];
    const float* sew    = (const float*)d_in[10];
    const float* sdw    = (const float*)d_in[11];
    const float* sb     = (const float*)d_in[12];
    float* out = (float*)d_out;

    k_reset<<<128, 256>>>();
    k_fused<<<128, 256>>>(data, graphs, edges, pos, dv, dw, db,
                          ew, ebias, sew, sdw, sb, out);
}

// round 13
// speedup vs baseline: 3.0279x; 3.0279x over previous
#include <cuda_runtime.h>
#include <cuda_bf16.h>
#include <cstdint>

#define NN   128
#define DD   128
#define EE   128
#define NG   8
#define VDIM 300

// ---------------- device scratch (allocation-free) ----------------
__device__ float g_base[NN * DD];
__device__ float g_vacc[NG][NN * DD];      // base + child-transform sums (dataflow acc)
__device__ float g_w2[NG][DD];
__device__ float g_cconst[NG];
__device__ float g_dscore;
__device__ int   g_cnt[NG][NN];            // child-completion counters (zeroed in K1)
__device__ int   g_par[NG][NN];
__device__ int   g_cc[NG][NN];
__device__ unsigned char g_inpath[NG][NN];
__device__ int   g_plen[NG];
__device__ int   g_plist[NG][NN];
__device__ int   g_pedge[NG][NN];

// ---------------- helpers ----------------
__device__ __forceinline__ float warp_red(float v) {
    for (int o = 16; o; o >>= 1) v += __shfl_xor_sync(0xffffffffu, v, o);
    return v;
}

// y[k0..3] = sum_d v[d]*W[d*DD+k0..3]; v lane-distributed float4 (lane q owns d 4q..4q+3)
// unroll 4 -> 16 independent LDG.128 in flight, compact code.
__device__ __forceinline__ float4 matvec(const float* __restrict__ W, float4 v, int k0) {
    float y0 = 0.f, y1 = 0.f, y2 = 0.f, y3 = 0.f;
    const float* Wl = W + k0;
#pragma unroll 4
    for (int q = 0; q < 32; q++) {
        float a0 = __shfl_sync(0xffffffffu, v.x, q);
        float a1 = __shfl_sync(0xffffffffu, v.y, q);
        float a2 = __shfl_sync(0xffffffffu, v.z, q);
        float a3 = __shfl_sync(0xffffffffu, v.w, q);
        float4 w0 = __ldg((const float4*)(Wl + (4 * q + 0) * DD));
        float4 w1 = __ldg((const float4*)(Wl + (4 * q + 1) * DD));
        float4 w2 = __ldg((const float4*)(Wl + (4 * q + 2) * DD));
        float4 w3 = __ldg((const float4*)(Wl + (4 * q + 3) * DD));
        y0 += a0 * w0.x + a1 * w1.x + a2 * w2.x + a3 * w3.x;
        y1 += a0 * w0.y + a1 * w1.y + a2 * w2.y + a3 * w3.y;
        y2 += a0 * w0.z + a1 * w1.z + a2 * w2.z + a3 * w3.z;
        y3 += a0 * w0.w + a1 * w1.w + a2 * w2.w + a3 * w3.w;
    }
    return make_float4(y0, y1, y2, y3);
}

// =============== K1: base + replicate + (CTAs 0..7) parse + fold + dscore ===============
__global__ void __launch_bounds__(256)
k_prep(const int* __restrict__ data, const int* __restrict__ graphs,
       const int* __restrict__ edges, const int* __restrict__ posp,
       const float* __restrict__ dv, const float* __restrict__ dw,
       const float* __restrict__ db, const float* __restrict__ ew,
       const float* __restrict__ ebias, const float* __restrict__ sew,
       const float* __restrict__ sdw, const float* __restrict__ sb) {
    __shared__ float s_dv[VDIM];
    __shared__ float s_half[2][DD];
    __shared__ float s_red[DD];
    __shared__ int s_par[NN], s_cc[NN];
    __shared__ unsigned s_rm[4];

    int b = blockIdx.x, t = threadIdx.x;
    int wid = t >> 5, lane = t & 31;

    // ---- base embedding for node b ----
    const float* vr = dv + (size_t)data[b] * VDIM;
    for (int i = t; i < VDIM; i += 256) s_dv[i] = vr[i];
    __syncthreads();
    {
        int k = t & 127, half = t >> 7;
        float acc = 0.f;
        int vs = half * 150, ve = vs + 150;
#pragma unroll 10
        for (int v = vs; v < ve; v++) acc += s_dv[v] * __ldg(dw + v * DD + k);
        s_half[half][k] = acc;
    }
    __syncthreads();
    float bval = 0.f;
    if (t < DD) {
        bval = s_half[0][t] + s_half[1][t] + db[t];
        g_base[b * DD + t] = bval;
#pragma unroll
        for (int g = 0; g < NG; g++) g_vacc[g][b * DD + t] = bval;
    }

    // ---- dscore: the CTA owning node pos ----
    int pos = *posp;
    if (b == pos) {
        if (t < DD) s_red[t] = bval * sdw[t];
        __syncthreads();
        for (int s = 64; s > 0; s >>= 1) {
            if (t < s) s_red[t] += s_red[t + s];
            __syncthreads();
        }
        if (t == 0) g_dscore = s_red[0] + sb[0];
    }

    // ---- parse + fold: CTAs 0..7 ----
    if (b < NG) {
        int g = b;
        if (t < NN) {
            int off = graphs[g * NN + t];
            bool isroot = (off == 0);
            int par = isroot ? -1 : ((t + off < NN) ? t + off : -1);
            unsigned bm = __ballot_sync(0xffffffffu, isroot);
            if (lane == 0) s_rm[wid] = bm;
            s_par[t] = par; s_cc[t] = 0;
        }
        __syncthreads();
        if (t == 0) {
            // faithful root chaining: effective parent of r_i = r_i + r_{i+1}
            int prev = -1;
            for (int q = 0; q < 4; q++) {
                unsigned mm = s_rm[q];
                while (mm) {
                    int bb = __ffs(mm) - 1; mm &= mm - 1;
                    int r = q * 32 + bb;
                    if (prev >= 0) { int p = prev + r; s_par[prev] = (p < NN) ? p : -1; }
                    prev = r;
                }
            }
            s_par[prev] = -1;   // final root
        }
        __syncthreads();
        if (t < NN) { int p = s_par[t]; if (p >= 0) atomicAdd(&s_cc[p], 1); }
        __syncthreads();
        if (t == 0) {
            int plen = 0, p = pos;
            while (p >= 0) {
                g_plist[g][plen] = p;
                g_pedge[g][plen] = edges[p];
                plen++;
                p = s_par[p];
            }
            g_plen[g] = plen;
        }
        __syncthreads();
        if (t < NN) {
            g_par[g][t] = s_par[t];
            g_cc[g][t] = s_cc[t];
            g_inpath[g][t] = 0;
            g_cnt[g][t] = 0;
        }
        __syncthreads();
        int plen = g_plen[g];
        if (t == 0)
            for (int i = 0; i < plen; i++) g_inpath[g][g_plist[g][i]] = 1;

        // ---- fold: w2[d] = sum_k W[er][d,k]*sew[k]; cconst = b[er].sew ----
        int er = g_pedge[g][plen - 1];
        if (t < DD) s_red[t] = sew[t];       // stage sew
        __syncthreads();
        if (t < DD) {
            const float4* Wr = (const float4*)(ew + (size_t)er * (DD * DD) + t * DD);
            float acc = 0.f;
#pragma unroll 8
            for (int q = 0; q < 32; q++) {
                float4 wq = __ldg(Wr + q);
                acc += wq.x * s_red[4 * q] + wq.y * s_red[4 * q + 1]
                     + wq.z * s_red[4 * q + 2] + wq.w * s_red[4 * q + 3];
            }
            g_w2[g][t] = acc;
        }
        __syncthreads();
        if (t < DD) s_red[t] = ebias[er * DD + t] * sew[t];
        __syncthreads();
        for (int s = 64; s > 0; s >>= 1) {
            if (t < s) s_red[t] += s_red[t + s];
            __syncthreads();
        }
        if (t == 0) g_cconst[g] = s_red[0];
    }
}

// =============== K2: dataflow vector pass (R6-proven), warp = (graph, node) ===============
__global__ void __launch_bounds__(256)
k_vecflow(const int* __restrict__ edges,
          const float* __restrict__ ew,
          const float* __restrict__ eb) {
    int w = (blockIdx.x << 3) + (threadIdx.x >> 5);   // 0..1023
    int lane = threadIdx.x & 31;
    int g = w >> 7, n = w & 127;
    int k0 = lane * 4;

    if (g_inpath[g][n]) return;                       // path nodes consumed by K3
    int par = g_par[g][n];
    int cc = g_cc[g][n];

    if (cc > 0) {
        int tgt = cc * 32;
        if (lane == 0) {
            while (atomicAdd(&g_cnt[g][n], 0) < tgt) { }
        }
        __syncwarp();
        __threadfence();
    }

    float4 v = __ldcg((const float4*)(&g_vacc[g][n * DD] + k0));
    if (cc > 0) {
        v.x = fmaxf(v.x, 0.f); v.y = fmaxf(v.y, 0.f);
        v.z = fmaxf(v.z, 0.f); v.w = fmaxf(v.w, 0.f);
    }

    if (par >= 0) {
        int e = edges[n];
        float4 bb = *(const float4*)(eb + e * DD + k0);
        float4 y = matvec(ew + (size_t)e * (DD * DD), v, k0);
        y.x += bb.x; y.y += bb.y; y.z += bb.z; y.w += bb.w;
        float* dst = &g_vacc[g][par * DD] + k0;
        atomicAdd(dst + 0, y.x); atomicAdd(dst + 1, y.y);
        atomicAdd(dst + 2, y.z); atomicAdd(dst + 3, y.w);
        __threadfence();
        atomicAdd(&g_cnt[g][par], 1);                 // every lane -> target cc*32
    }
}

// =============== K3: chains — 1024 warps, 1 chain each, reg-resident state ===============
__global__ void __launch_bounds__(256)
k_chain(const float* __restrict__ ew,
        const float* __restrict__ eb,
        const float* __restrict__ sew,
        float* __restrict__ out) {
    int b = blockIdx.x;
    int wid = threadIdx.x >> 5, lane = threadIdx.x & 31;
    int k0 = lane * 4;
    int cg = b >> 4;
    int e = ((b & 15) << 3) + wid;

    int plen = g_plen[cg];
    int pos0 = g_plist[cg][0];

    // v0 = vacc[pos] (base + non-path child transforms), relu iff internal
    float4 v0 = __ldcg((const float4*)(&g_vacc[cg][pos0 * DD] + k0));
    if (g_cc[cg][pos0] > 0) {
        v0.x = fmaxf(v0.x, 0.f); v0.y = fmaxf(v0.y, 0.f);
        v0.z = fmaxf(v0.z, 0.f); v0.w = fmaxf(v0.w, 0.f);
    }

    // step 0: per-e transform (the unknown-edge branch)
    float4 bb = *(const float4*)(eb + e * DD + k0);
    float4 y = matvec(ew + (size_t)e * (DD * DD), v0, k0);
    y.x += bb.x; y.y += bb.y; y.z += bb.z; y.w += bb.w;

    float dsc = g_dscore;
    if (plen == 1) {
        float4 sv = *(const float4*)(sew + k0);
        float p = warp_red(y.x * sv.x + y.y * sv.y + y.z * sv.z + y.w * sv.w);
        if (lane == 0) out[cg * EE + e] = dsc + p;
        return;
    }

    float4 u1 = __ldcg((const float4*)(&g_vacc[cg][g_plist[cg][1] * DD] + k0));
    float4 m;
    m.x = fmaxf(y.x + u1.x, 0.f); m.y = fmaxf(y.y + u1.y, 0.f);
    m.z = fmaxf(y.z + u1.z, 0.f); m.w = fmaxf(y.w + u1.w, 0.f);

    for (int i = 2; i < plen; i++) {
        int eid = __ldg(&g_pedge[cg][i - 1]);
        float4 bi = *(const float4*)(eb + eid * DD + k0);
        float4 tt = matvec(ew + (size_t)eid * (DD * DD), m, k0);
        float4 u4 = __ldcg((const float4*)(&g_vacc[cg][g_plist[cg][i] * DD] + k0));
        m.x = fmaxf(tt.x + bi.x + u4.x, 0.f);
        m.y = fmaxf(tt.y + bi.y + u4.y, 0.f);
        m.z = fmaxf(tt.z + bi.z + u4.z, 0.f);
        m.w = fmaxf(tt.w + bi.w + u4.w, 0.f);
    }

    float4 w2v = *(const float4*)(&g_w2[cg][0] + k0);
    float p = warp_red(m.x * w2v.x + m.y * w2v.y + m.z * w2v.z + m.w * w2v.w);
    if (lane == 0) out[cg * EE + e] = dsc + g_cconst[cg] + p;
}

// =============== launcher: 3 kernels ===============
extern "C" void kernel_launch(void* const* d_in, const int* in_sizes, int n_in,
                              void* d_out, int out_size) {
    const int*   data   = (const int*)d_in[0];
    const int*   graphs = (const int*)d_in[2];
    const int*   edges  = (const int*)d_in[3];
    const int*   pos    = (const int*)d_in[4];
    const float* dv     = (const float*)d_in[5];
    const float* dw     = (const float*)d_in[6];
    const float* db     = (const float*)d_in[7];
    const float* ew     = (const float*)d_in[8];
    const float* ebias  = (const float*)d_in[9];
    const float* sew    = (const float*)d_in[10];
    const float* sdw    = (const float*)d_in[11];
    const float* sb     = (const float*)d_in[12];
    float* out = (float*)d_out;

    k_prep   <<<NN, 256>>>(data, graphs, edges, pos, dv, dw, db,
                           ew, ebias, sew, sdw, sb);
    k_vecflow<<<128, 256>>>(edges, ew, ebias);
    k_chain  <<<128, 256>>>(ew, ebias, sew, out);
}